// round 1
// baseline (speedup 1.0000x reference)
#include <cuda_runtime.h>
#include <cuda_bf16.h>
#include <math.h>

#define N_NODES 50000
#define HDIM 96
#define E_EDGES 800000
#define E_TOT (E_EDGES + N_NODES)

// ---------------- device scratch (static allocation, allowed) ----------------
__device__ int   g_deg[N_NODES];
__device__ float g_dinv[N_NODES];
__device__ int   g_rowptr[N_NODES + 1];
__device__ int   g_cursor[N_NODES];
__device__ int   g_col[E_TOT];
__device__ float g_h1[(size_t)N_NODES * HDIM];   // xW result / h2@W2 result
__device__ float g_h2[(size_t)N_NODES * HDIM];   // layer-1 output (post LN/PReLU)

// ---------------- setup kernels ----------------
__global__ void k_zero_deg() {
    int i = blockIdx.x * blockDim.x + threadIdx.x;
    if (i < N_NODES) g_deg[i] = 0;
}

__global__ void k_degree(const int* __restrict__ dst, int E) {
    int i = blockIdx.x * blockDim.x + threadIdx.x;
    if (i < E) atomicAdd(&g_deg[dst[i]], 1);
}

__global__ void k_dinv() {
    int i = blockIdx.x * blockDim.x + threadIdx.x;
    if (i < N_NODES) {
        int d = g_deg[i] + 1;  // + self loop
        g_dinv[i] = rsqrtf((float)d);
    }
}

// single-block exclusive scan of (deg[i]+1) -> rowptr, cursor
__global__ void k_scan() {
    __shared__ int part[1024];
    const int n = N_NODES;
    const int CH = (n + 1023) / 1024;  // 49
    int t = threadIdx.x;
    int lo = t * CH;
    int hi = lo + CH; if (hi > n) hi = n;
    int s = 0;
    for (int i = lo; i < hi; i++) s += g_deg[i] + 1;
    part[t] = s;
    __syncthreads();
    // Kogge-Stone inclusive scan
    for (int off = 1; off < 1024; off <<= 1) {
        int v = (t >= off) ? part[t - off] : 0;
        __syncthreads();
        part[t] += v;
        __syncthreads();
    }
    int run = (t == 0) ? 0 : part[t - 1];
    for (int i = lo; i < hi; i++) {
        g_rowptr[i] = run;
        g_cursor[i] = run;
        run += g_deg[i] + 1;
    }
    if (lo < n && hi == n) g_rowptr[n] = run;
}

__global__ void k_fill(const int* __restrict__ src, const int* __restrict__ dst, int E) {
    int i = blockIdx.x * blockDim.x + threadIdx.x;
    if (i >= E + N_NODES) return;
    int d, s;
    if (i < E) { d = dst[i]; s = src[i]; }
    else       { d = i - E;  s = i - E; }   // self loop
    int p = atomicAdd(&g_cursor[d], 1);
    g_col[p] = s;
}

// ---------------- GEMM: C[M,96] = A[M,K] @ B[K,96] ----------------
#define BM 128
#define BK 32
#define BN 96

__global__ __launch_bounds__(256, 2)
void gemm_kernel(const float* __restrict__ A, const float* __restrict__ B,
                 float* __restrict__ C, int M, int K) {
    __shared__ float As[BM][BK + 1];
    __shared__ float Bs[BK][BN];

    int tid = threadIdx.x;
    int m0 = blockIdx.x * BM;
    int ty = tid >> 4;     // 0..15 row group (8 rows each)
    int tx = tid & 15;     // 0..15 col group (6 cols each)

    float acc[8][6];
#pragma unroll
    for (int i = 0; i < 8; i++)
#pragma unroll
        for (int j = 0; j < 6; j++) acc[i][j] = 0.0f;

    for (int k0 = 0; k0 < K; k0 += BK) {
        // A tile: 128x32 floats = 1024 float4, 256 threads -> 4 float4 each
#pragma unroll
        for (int r = 0; r < 4; r++) {
            int idx = tid + r * 256;       // 0..1023
            int m  = idx >> 3;             // 0..127
            int kq = (idx & 7) << 2;       // 0,4,...,28
            float4 v = make_float4(0.f, 0.f, 0.f, 0.f);
            if (m0 + m < M)
                v = *reinterpret_cast<const float4*>(A + (size_t)(m0 + m) * K + k0 + kq);
            As[m][kq + 0] = v.x; As[m][kq + 1] = v.y;
            As[m][kq + 2] = v.z; As[m][kq + 3] = v.w;
        }
        // B tile: 32x96 = 3072 floats -> 12 each
#pragma unroll
        for (int r = 0; r < 12; r++) {
            int idx = tid + r * 256;
            int kk = idx / BN;
            int c  = idx - kk * BN;
            Bs[kk][c] = B[(size_t)(k0 + kk) * BN + c];
        }
        __syncthreads();
#pragma unroll
        for (int kk = 0; kk < BK; kk++) {
            float a[8], b[6];
#pragma unroll
            for (int i = 0; i < 8; i++) a[i] = As[ty * 8 + i][kk];
#pragma unroll
            for (int j = 0; j < 6; j++) b[j] = Bs[kk][tx * 6 + j];
#pragma unroll
            for (int i = 0; i < 8; i++)
#pragma unroll
                for (int j = 0; j < 6; j++) acc[i][j] = fmaf(a[i], b[j], acc[i][j]);
        }
        __syncthreads();
    }
#pragma unroll
    for (int i = 0; i < 8; i++) {
        int m = m0 + ty * 8 + i;
        if (m < M) {
#pragma unroll
            for (int j = 0; j < 6; j++)
                C[(size_t)m * BN + tx * 6 + j] = acc[i][j];
        }
    }
}

// ---------------- fused aggregate + bias + LayerNorm + PReLU ----------------
// one warp per node; 3 features per lane (96 = 3*32)
__global__ __launch_bounds__(256)
void agg_ln_kernel(const float* __restrict__ h,
                   const float* __restrict__ bias,
                   const float* __restrict__ gamma,
                   const float* __restrict__ beta,
                   const float* __restrict__ alpha,
                   float* __restrict__ out) {
    int gw = (blockIdx.x * blockDim.x + threadIdx.x) >> 5;
    int lane = threadIdx.x & 31;
    if (gw >= N_NODES) return;
    int n = gw;

    int beg = g_rowptr[n];
    int end = g_rowptr[n + 1];
    float dn = g_dinv[n];

    float a0 = 0.f, a1 = 0.f, a2 = 0.f;
    for (int j = beg; j < end; j++) {
        int s = g_col[j];
        float w = dn * g_dinv[s];
        const float* hs = h + (size_t)s * HDIM;
        a0 = fmaf(hs[lane], w, a0);
        a1 = fmaf(hs[lane + 32], w, a1);
        a2 = fmaf(hs[lane + 64], w, a2);
    }
    a0 += bias[lane]; a1 += bias[lane + 32]; a2 += bias[lane + 64];

    // mean
    float s = a0 + a1 + a2;
#pragma unroll
    for (int o = 16; o; o >>= 1) s += __shfl_xor_sync(0xffffffffu, s, o);
    float mu = s * (1.0f / 96.0f);
    float c0 = a0 - mu, c1 = a1 - mu, c2 = a2 - mu;
    // variance
    float v = c0 * c0 + c1 * c1 + c2 * c2;
#pragma unroll
    for (int o = 16; o; o >>= 1) v += __shfl_xor_sync(0xffffffffu, v, o);
    float inv = rsqrtf(v * (1.0f / 96.0f) + 1e-5f);

    float y0 = c0 * inv * gamma[lane]      + beta[lane];
    float y1 = c1 * inv * gamma[lane + 32] + beta[lane + 32];
    float y2 = c2 * inv * gamma[lane + 64] + beta[lane + 64];
    y0 = (y0 >= 0.f) ? y0 : alpha[lane]      * y0;
    y1 = (y1 >= 0.f) ? y1 : alpha[lane + 32] * y1;
    y2 = (y2 >= 0.f) ? y2 : alpha[lane + 64] * y2;

    float* op = out + (size_t)n * HDIM;
    op[lane] = y0; op[lane + 32] = y1; op[lane + 64] = y2;
}

// ---------------- launch ----------------
static inline int cdiv(int a, int b) { return (a + b - 1) / b; }

extern "C" void kernel_launch(void* const* d_in, const int* in_sizes, int n_in,
                              void* d_out, int out_size) {
    const float* x   = (const float*)d_in[0];
    const int*   ei  = (const int*)d_in[1];
    const float* W1  = (const float*)d_in[2];
    const float* b1  = (const float*)d_in[3];
    const float* W2  = (const float*)d_in[4];
    const float* b2  = (const float*)d_in[5];
    const float* g1  = (const float*)d_in[6];
    const float* be1 = (const float*)d_in[7];
    const float* g2  = (const float*)d_in[8];
    const float* be2 = (const float*)d_in[9];
    const float* a   = (const float*)d_in[10];
    float* out = (float*)d_out;

    int E = in_sizes[1] / 2;
    const int* src = ei;
    const int* dst = ei + E;

    // Build graph structure (CSR with self loops) — reused for both layers
    k_zero_deg<<<cdiv(N_NODES, 256), 256>>>();
    k_degree<<<cdiv(E, 256), 256>>>(dst, E);
    k_dinv<<<cdiv(N_NODES, 256), 256>>>();
    k_scan<<<1, 1024>>>();
    k_fill<<<cdiv(E + N_NODES, 256), 256>>>(src, dst, E);

    float* h1; cudaGetSymbolAddress((void**)&h1, g_h1);
    float* h2; cudaGetSymbolAddress((void**)&h2, g_h2);

    // Layer 1: h1 = x @ W1 ; h2 = prelu(ln(aggregate(h1) + b1))
    gemm_kernel<<<cdiv(N_NODES, BM), 256>>>(x, W1, h1, N_NODES, 128);
    agg_ln_kernel<<<cdiv(N_NODES * 32, 256), 256>>>(h1, b1, g1, be1, a, h2);

    // Layer 2: h1 = h2 @ W2 ; out = prelu(ln(aggregate(h1) + b2))
    gemm_kernel<<<cdiv(N_NODES, BM), 256>>>(h2, W2, h1, N_NODES, HDIM);
    agg_ln_kernel<<<cdiv(N_NODES * 32, 256), 256>>>(h1, b2, g2, be2, a, out);
}

// round 2
// speedup vs baseline: 1.4053x; 1.4053x over previous
#include <cuda_runtime.h>
#include <cuda_bf16.h>
#include <math.h>

#define N_NODES 50000
#define HDIM 96
#define E_EDGES 800000
#define E_TOT (E_EDGES + N_NODES)
#define SCAN_B 256
#define SCAN_NBLK ((N_NODES + SCAN_B - 1) / SCAN_B)   // 196

// ---------------- device scratch (static allocation, allowed) ----------------
__device__ int   g_deg[N_NODES];
__device__ float g_dinv[N_NODES];
__device__ int   g_rowptr[N_NODES + 1];
__device__ int   g_cursor[N_NODES];
__device__ int   g_col[E_TOT];
__device__ int   g_blocksum[SCAN_NBLK];
__device__ int   g_blockoff[SCAN_NBLK];
__device__ float g_h1[(size_t)N_NODES * HDIM];   // xW result / h2@W2 result
__device__ float g_h2[(size_t)N_NODES * HDIM];   // layer-1 output (post LN/PReLU)

// ---------------- setup kernels ----------------
__global__ void k_zero_deg() {
    int i = blockIdx.x * blockDim.x + threadIdx.x;
    if (i < N_NODES) g_deg[i] = 0;
}

__global__ void k_degree(const int* __restrict__ dst, int E) {
    int i = blockIdx.x * blockDim.x + threadIdx.x;
    if (i < E) atomicAdd(&g_deg[dst[i]], 1);
}

__global__ void k_dinv() {
    int i = blockIdx.x * blockDim.x + threadIdx.x;
    if (i < N_NODES) {
        int d = g_deg[i] + 1;  // + self loop
        g_dinv[i] = rsqrtf((float)d);
    }
}

// --- parallel 3-phase exclusive scan of (deg[i]+1) -> rowptr, cursor ---
// phase 1: per-block reduction
__global__ void k_scan1() {
    __shared__ int sh[SCAN_B];
    int i = blockIdx.x * SCAN_B + threadIdx.x;
    int v = (i < N_NODES) ? (g_deg[i] + 1) : 0;
    sh[threadIdx.x] = v;
    __syncthreads();
#pragma unroll
    for (int o = SCAN_B / 2; o > 0; o >>= 1) {
        if (threadIdx.x < o) sh[threadIdx.x] += sh[threadIdx.x + o];
        __syncthreads();
    }
    if (threadIdx.x == 0) g_blocksum[blockIdx.x] = sh[0];
}

// phase 2: single-block exclusive scan of the 196 block sums
__global__ void k_scan2() {
    __shared__ int sh[SCAN_B];
    int t = threadIdx.x;
    int v = (t < SCAN_NBLK) ? g_blocksum[t] : 0;
    sh[t] = v;
    __syncthreads();
    // Kogge-Stone inclusive
#pragma unroll
    for (int o = 1; o < SCAN_B; o <<= 1) {
        int u = (t >= o) ? sh[t - o] : 0;
        __syncthreads();
        sh[t] += u;
        __syncthreads();
    }
    if (t < SCAN_NBLK) g_blockoff[t] = sh[t] - v;   // exclusive
}

// phase 3: per-block exclusive scan + block offset -> rowptr, cursor
__global__ void k_scan3() {
    __shared__ int sh[SCAN_B];
    int t = threadIdx.x;
    int i = blockIdx.x * SCAN_B + t;
    int v = (i < N_NODES) ? (g_deg[i] + 1) : 0;
    sh[t] = v;
    __syncthreads();
#pragma unroll
    for (int o = 1; o < SCAN_B; o <<= 1) {
        int u = (t >= o) ? sh[t - o] : 0;
        __syncthreads();
        sh[t] += u;
        __syncthreads();
    }
    if (i < N_NODES) {
        int pref = g_blockoff[blockIdx.x] + sh[t] - v;   // exclusive prefix
        g_rowptr[i] = pref;
        g_cursor[i] = pref;
        if (i == N_NODES - 1) g_rowptr[N_NODES] = pref + v;
    }
}

__global__ void k_fill(const int* __restrict__ src, const int* __restrict__ dst, int E) {
    int i = blockIdx.x * blockDim.x + threadIdx.x;
    if (i >= E + N_NODES) return;
    int d, s;
    if (i < E) { d = dst[i]; s = src[i]; }
    else       { d = i - E;  s = i - E; }   // self loop
    int p = atomicAdd(&g_cursor[d], 1);
    g_col[p] = s;
}

// ---------------- GEMM: C[M,96] = A[M,K] @ B[K,96] ----------------
#define BM 128
#define BK 32
#define BN 96

__global__ __launch_bounds__(256, 2)
void gemm_kernel(const float* __restrict__ A, const float* __restrict__ B,
                 float* __restrict__ C, int M, int K) {
    __shared__ float As[BM][BK + 1];
    __shared__ float Bs[BK][BN];

    int tid = threadIdx.x;
    int m0 = blockIdx.x * BM;
    int ty = tid >> 4;     // 0..15 row group (8 rows each)
    int tx = tid & 15;     // 0..15 col group (6 cols each)

    float acc[8][6];
#pragma unroll
    for (int i = 0; i < 8; i++)
#pragma unroll
        for (int j = 0; j < 6; j++) acc[i][j] = 0.0f;

    for (int k0 = 0; k0 < K; k0 += BK) {
        // A tile: 128x32 floats = 1024 float4, 256 threads -> 4 float4 each
#pragma unroll
        for (int r = 0; r < 4; r++) {
            int idx = tid + r * 256;       // 0..1023
            int m  = idx >> 3;             // 0..127
            int kq = (idx & 7) << 2;       // 0,4,...,28
            float4 v = make_float4(0.f, 0.f, 0.f, 0.f);
            if (m0 + m < M)
                v = *reinterpret_cast<const float4*>(A + (size_t)(m0 + m) * K + k0 + kq);
            As[m][kq + 0] = v.x; As[m][kq + 1] = v.y;
            As[m][kq + 2] = v.z; As[m][kq + 3] = v.w;
        }
        // B tile: 32x96 = 3072 floats -> 12 each
#pragma unroll
        for (int r = 0; r < 12; r++) {
            int idx = tid + r * 256;
            int kk = idx / BN;
            int c  = idx - kk * BN;
            Bs[kk][c] = B[(size_t)(k0 + kk) * BN + c];
        }
        __syncthreads();
#pragma unroll
        for (int kk = 0; kk < BK; kk++) {
            float a[8], b[6];
#pragma unroll
            for (int i = 0; i < 8; i++) a[i] = As[ty * 8 + i][kk];
#pragma unroll
            for (int j = 0; j < 6; j++) b[j] = Bs[kk][tx * 6 + j];
#pragma unroll
            for (int i = 0; i < 8; i++)
#pragma unroll
                for (int j = 0; j < 6; j++) acc[i][j] = fmaf(a[i], b[j], acc[i][j]);
        }
        __syncthreads();
    }
#pragma unroll
    for (int i = 0; i < 8; i++) {
        int m = m0 + ty * 8 + i;
        if (m < M) {
#pragma unroll
            for (int j = 0; j < 6; j++)
                C[(size_t)m * BN + tx * 6 + j] = acc[i][j];
        }
    }
}

// ---------------- fused aggregate + bias + LayerNorm + PReLU ----------------
// one warp per node; 3 features per lane (96 = 3*32)
__global__ __launch_bounds__(256)
void agg_ln_kernel(const float* __restrict__ h,
                   const float* __restrict__ bias,
                   const float* __restrict__ gamma,
                   const float* __restrict__ beta,
                   const float* __restrict__ alpha,
                   float* __restrict__ out) {
    int gw = (blockIdx.x * blockDim.x + threadIdx.x) >> 5;
    int lane = threadIdx.x & 31;
    if (gw >= N_NODES) return;
    int n = gw;

    int beg = g_rowptr[n];
    int end = g_rowptr[n + 1];
    float dn = g_dinv[n];

    float a0 = 0.f, a1 = 0.f, a2 = 0.f;
    for (int j = beg; j < end; j++) {
        int s = g_col[j];
        float w = dn * g_dinv[s];
        const float* hs = h + (size_t)s * HDIM;
        a0 = fmaf(hs[lane], w, a0);
        a1 = fmaf(hs[lane + 32], w, a1);
        a2 = fmaf(hs[lane + 64], w, a2);
    }
    a0 += bias[lane]; a1 += bias[lane + 32]; a2 += bias[lane + 64];

    // mean
    float s = a0 + a1 + a2;
#pragma unroll
    for (int o = 16; o; o >>= 1) s += __shfl_xor_sync(0xffffffffu, s, o);
    float mu = s * (1.0f / 96.0f);
    float c0 = a0 - mu, c1 = a1 - mu, c2 = a2 - mu;
    // variance
    float v = c0 * c0 + c1 * c1 + c2 * c2;
#pragma unroll
    for (int o = 16; o; o >>= 1) v += __shfl_xor_sync(0xffffffffu, v, o);
    float inv = rsqrtf(v * (1.0f / 96.0f) + 1e-5f);

    float y0 = c0 * inv * gamma[lane]      + beta[lane];
    float y1 = c1 * inv * gamma[lane + 32] + beta[lane + 32];
    float y2 = c2 * inv * gamma[lane + 64] + beta[lane + 64];
    y0 = (y0 >= 0.f) ? y0 : alpha[lane]      * y0;
    y1 = (y1 >= 0.f) ? y1 : alpha[lane + 32] * y1;
    y2 = (y2 >= 0.f) ? y2 : alpha[lane + 64] * y2;

    float* op = out + (size_t)n * HDIM;
    op[lane] = y0; op[lane + 32] = y1; op[lane + 64] = y2;
}

// ---------------- launch ----------------
static inline int cdiv(int a, int b) { return (a + b - 1) / b; }

extern "C" void kernel_launch(void* const* d_in, const int* in_sizes, int n_in,
                              void* d_out, int out_size) {
    const float* x   = (const float*)d_in[0];
    const int*   ei  = (const int*)d_in[1];
    const float* W1  = (const float*)d_in[2];
    const float* b1  = (const float*)d_in[3];
    const float* W2  = (const float*)d_in[4];
    const float* b2  = (const float*)d_in[5];
    const float* g1  = (const float*)d_in[6];
    const float* be1 = (const float*)d_in[7];
    const float* g2  = (const float*)d_in[8];
    const float* be2 = (const float*)d_in[9];
    const float* a   = (const float*)d_in[10];
    float* out = (float*)d_out;

    int E = in_sizes[1] / 2;
    const int* src = ei;
    const int* dst = ei + E;

    // Build graph structure (CSR with self loops) — reused for both layers
    k_zero_deg<<<cdiv(N_NODES, 256), 256>>>();
    k_degree<<<cdiv(E, 256), 256>>>(dst, E);
    k_dinv<<<cdiv(N_NODES, 256), 256>>>();
    k_scan1<<<SCAN_NBLK, SCAN_B>>>();
    k_scan2<<<1, SCAN_B>>>();
    k_scan3<<<SCAN_NBLK, SCAN_B>>>();
    k_fill<<<cdiv(E + N_NODES, 256), 256>>>(src, dst, E);

    float* h1; cudaGetSymbolAddress((void**)&h1, g_h1);
    float* h2; cudaGetSymbolAddress((void**)&h2, g_h2);

    // Layer 1: h1 = x @ W1 ; h2 = prelu(ln(aggregate(h1) + b1))
    gemm_kernel<<<cdiv(N_NODES, BM), 256>>>(x, W1, h1, N_NODES, 128);
    agg_ln_kernel<<<cdiv(N_NODES * 32, 256), 256>>>(h1, b1, g1, be1, a, h2);

    // Layer 2: h1 = h2 @ W2 ; out = prelu(ln(aggregate(h1) + b2))
    gemm_kernel<<<cdiv(N_NODES, BM), 256>>>(h2, W2, h1, N_NODES, HDIM);
    agg_ln_kernel<<<cdiv(N_NODES * 32, 256), 256>>>(h1, b2, g2, be2, a, out);
}